// round 11
// baseline (speedup 1.0000x reference)
#include <cuda_runtime.h>
#include <cuda_bf16.h>
#include <math.h>
#include <stdint.h>

#define NB 8
#define NT 2048
#define NC 1024
#define NH 128
#define NBT (NB*NT)

// bf16 hi/lo split scratch
__device__ __nv_bfloat16 g_Xh[NBT*NC];    // x hi/lo planes (from split_pass)
__device__ __nv_bfloat16 g_Xl[NBT*NC];
__device__ __nv_bfloat16 g_Wh[3*NH*NC];   // Wq|Wk|Wv hi/lo planes
__device__ __nv_bfloat16 g_Wl[3*NH*NC];
__device__ __nv_bfloat16 g_Qh[NBT*NH];    // Q * scale, [b][t][d]
__device__ __nv_bfloat16 g_Ql[NBT*NH];
__device__ __nv_bfloat16 g_Kh[NBT*NH];    // [b][t][d]
__device__ __nv_bfloat16 g_Kl[NBT*NH];
__device__ __nv_bfloat16 g_Vth[NB*NH*NT]; // transposed: [b][d][t]
__device__ __nv_bfloat16 g_Vtl[NB*NH*NT];

// ===========================================================================
// Helpers (generic sm_80+ PTX)
// ===========================================================================
__device__ __forceinline__ void mma_bf16(float* d, const uint32_t* a, const uint32_t* b) {
    asm volatile(
        "mma.sync.aligned.m16n8k16.row.col.f32.bf16.bf16.f32 "
        "{%0,%1,%2,%3}, {%4,%5,%6,%7}, {%8,%9}, {%0,%1,%2,%3};"
        : "+f"(d[0]), "+f"(d[1]), "+f"(d[2]), "+f"(d[3])
        : "r"(a[0]), "r"(a[1]), "r"(a[2]), "r"(a[3]), "r"(b[0]), "r"(b[1]));
}
__device__ __forceinline__ void bsplit2(float x, float y, uint32_t& h, uint32_t& l) {
    __nv_bfloat162 hh = __floats2bfloat162_rn(x, y);
    float rx = x - __bfloat162float(hh.x);
    float ry = y - __bfloat162float(hh.y);
    __nv_bfloat162 ll = __floats2bfloat162_rn(rx, ry);
    h = *(uint32_t*)&hh;
    l = *(uint32_t*)&ll;
}
__device__ __forceinline__ uint32_t smem_u32(const void* p) {
    uint32_t a;
    asm("{ .reg .u64 t; cvta.to.shared.u64 t, %1; cvt.u32.u64 %0, t; }" : "=r"(a) : "l"(p));
    return a;
}
#define CPA16(dst, src) \
    asm volatile("cp.async.cg.shared.global [%0], [%1], 16;" :: "r"(dst), "l"(src))
#define CP_COMMIT asm volatile("cp.async.commit_group;" ::: "memory")
#define CP_WAIT(n) asm volatile("cp.async.wait_group %0;" :: "n"(n) : "memory")

// ===========================================================================
// Pre-pass: convert x and W to bf16 hi/lo planes (once).
// ===========================================================================
#define XBLK (NBT * NC / 4 / 256)      // 16384
#define WBLK (NH * NC / 4 / 256)       // 128 per weight matrix

__global__ __launch_bounds__(256, 8)
void split_pass(const float* __restrict__ x,
                const float* __restrict__ Wq,
                const float* __restrict__ Wk,
                const float* __restrict__ Wv) {
    const int bid = (int)blockIdx.x;
    const int tid = threadIdx.x;
    if (bid < XBLK) {
        size_t i = (size_t)bid * 256 + tid;          // float4 index
        float4 v = ((const float4*)x)[i];
        uint32_t h0, l0, h1, l1;
        bsplit2(v.x, v.y, h0, l0);
        bsplit2(v.z, v.w, h1, l1);
        ((uint2*)g_Xh)[i] = make_uint2(h0, h1);
        ((uint2*)g_Xl)[i] = make_uint2(l0, l1);
    } else {
        const int j = bid - XBLK;                    // 0..383
        const int widx = j / WBLK;
        const float* W = (widx == 0) ? Wq : (widx == 1) ? Wk : Wv;
        size_t i = (size_t)(j % WBLK) * 256 + tid;   // float4 idx within W
        float4 v = ((const float4*)W)[i];
        uint32_t h0, l0, h1, l1;
        bsplit2(v.x, v.y, h0, l0);
        bsplit2(v.z, v.w, h1, l1);
        size_t o = (size_t)widx * (NH * NC / 4) + i;
        ((uint2*)g_Wh)[o] = make_uint2(h0, h1);
        ((uint2*)g_Wl)[o] = make_uint2(l0, l1);
    }
}

// ===========================================================================
// QKV projection, bf16 3-term split GEMM (m16n8k16), pure cp.async mainloop.
// CTA: 128(M) x 128(N), K chunked by 32, 2-stage cp.async double buffer.
// Stage: Ah/Al/Bh/Bl planes, [128 rows][40 bf16] (80B rows, conflict-free).
// 2 CTAs/SM. Epilogue emits bf16 hi/lo Q (pre-scaled), K; V transposed.
// ===========================================================================
#define ROWW 20                       // u32 words per plane row (40 bf16)
#define PLANE (128 * ROWW)            // 2560 u32 per plane
#define STAGEW (4 * PLANE)            // words per stage
#define STAGEB (STAGEW * 4)           // 40960 bytes
#define QKV_SMEM (2 * STAGEB)         // 81920 bytes

__device__ __forceinline__ void qkv_load_stage(uint32_t sb, int st, int m0,
                                               int widx, int k0, int tid) {
    #pragma unroll
    for (int i = 0; i < 8; i++) {
        int c = tid + i * 256;
        int plane = c >> 9;                 // 0:Ah 1:Al 2:Bh 3:Bl
        int cc = c & 511;
        int row = cc >> 2, ch = cc & 3;
        const __nv_bfloat16* src;
        if (plane == 0)      src = g_Xh + (size_t)(m0 + row) * NC + k0 + ch * 8;
        else if (plane == 1) src = g_Xl + (size_t)(m0 + row) * NC + k0 + ch * 8;
        else if (plane == 2) src = g_Wh + ((size_t)widx * NH + row) * NC + k0 + ch * 8;
        else                 src = g_Wl + ((size_t)widx * NH + row) * NC + k0 + ch * 8;
        uint32_t dst = sb + (uint32_t)st * STAGEB + plane * (PLANE * 4) + row * 80 + ch * 16;
        CPA16(dst, src);
    }
}

__global__ __launch_bounds__(256, 2)
void qkv_mma_kernel() {
    extern __shared__ uint32_t smu[];
    const uint32_t sb = smem_u32(smu);

    const int widx = (int)blockIdx.y;
    const int tid  = threadIdx.x;
    const int wid  = tid >> 5;
    const int lane = tid & 31;
    const int g    = lane >> 2;
    const int tig  = lane & 3;
    const int m0   = blockIdx.x * 128;

    qkv_load_stage(sb, 0, m0, widx, 0, tid);
    CP_COMMIT;
    qkv_load_stage(sb, 1, m0, widx, 32, tid);
    CP_COMMIT;

    float acc[2][8][4];
    #pragma unroll
    for (int mf = 0; mf < 2; mf++)
        #pragma unroll
        for (int nf = 0; nf < 8; nf++)
            #pragma unroll
            for (int i = 0; i < 4; i++) acc[mf][nf][i] = 0.f;

    const int mrow  = (wid & 3) * 32 + g;
    const int nbase = (wid >> 2) * 64 + g;

    for (int c = 0; c < 32; c++) {
        const int st = c & 1;
        const uint32_t* Ah = smu + st * STAGEW;
        const uint32_t* Al = Ah + PLANE;
        const uint32_t* Bh = Ah + 2 * PLANE;
        const uint32_t* Bl = Ah + 3 * PLANE;

        CP_WAIT(1);          // chunk c's stage complete
        __syncthreads();

        #pragma unroll
        for (int ks = 0; ks < 2; ks++) {
            const int ko = ks * 8 + tig;
            uint32_t ahf[2][4], alf[2][4];
            #pragma unroll
            for (int mf = 0; mf < 2; mf++) {
                const int base = (mrow + mf * 16) * ROWW + ko;
                ahf[mf][0] = Ah[base];
                ahf[mf][1] = Ah[base + 8 * ROWW];
                ahf[mf][2] = Ah[base + 4];
                ahf[mf][3] = Ah[base + 8 * ROWW + 4];
                alf[mf][0] = Al[base];
                alf[mf][1] = Al[base + 8 * ROWW];
                alf[mf][2] = Al[base + 4];
                alf[mf][3] = Al[base + 8 * ROWW + 4];
            }
            #pragma unroll
            for (int nf = 0; nf < 8; nf++) {
                const int bb = (nbase + nf * 8) * ROWW + ko;
                uint32_t bh[2] = { Bh[bb], Bh[bb + 4] };
                uint32_t bl[2] = { Bl[bb], Bl[bb + 4] };
                #pragma unroll
                for (int mf = 0; mf < 2; mf++) {
                    mma_bf16(acc[mf][nf], ahf[mf], bh);
                    mma_bf16(acc[mf][nf], ahf[mf], bl);
                    mma_bf16(acc[mf][nf], alf[mf], bh);
                }
            }
        }

        __syncthreads();     // all warps done reading stage before overwrite
        if (c + 2 < 32) qkv_load_stage(sb, st, m0, widx, (c + 2) * 32, tid);
        CP_COMMIT;           // always commit (possibly empty) -> uniform groups
    }

    // ---- epilogue: bf16 hi/lo outputs for the attention kernel ----
    if (widx < 2) {
        __nv_bfloat16* oh = (widx == 0) ? g_Qh : g_Kh;
        __nv_bfloat16* ol = (widx == 0) ? g_Ql : g_Kl;
        const float sc = (widx == 0) ? 0.08838834764831845f : 1.0f;
        #pragma unroll
        for (int mf = 0; mf < 2; mf++) {
            const int crow = m0 + mrow + mf * 16;
            #pragma unroll
            for (int nf = 0; nf < 8; nf++) {
                const int ccol = (wid >> 2) * 64 + nf * 8 + tig * 2;
                uint32_t h01, l01, h23, l23;
                bsplit2(acc[mf][nf][0]*sc, acc[mf][nf][1]*sc, h01, l01);
                bsplit2(acc[mf][nf][2]*sc, acc[mf][nf][3]*sc, h23, l23);
                *(uint32_t*)&oh[(size_t)crow * NH + ccol]       = h01;
                *(uint32_t*)&ol[(size_t)crow * NH + ccol]       = l01;
                *(uint32_t*)&oh[(size_t)(crow + 8) * NH + ccol] = h23;
                *(uint32_t*)&ol[(size_t)(crow + 8) * NH + ccol] = l23;
            }
        }
    } else {
        // V: transpose to [d][t] via smem, then coalesced writes
        __nv_bfloat16* svh = (__nv_bfloat16*)smu;      // [128 d][136]
        __nv_bfloat16* svl = svh + 128 * 136;
        __syncthreads();
        #pragma unroll
        for (int mf = 0; mf < 2; mf++) {
            const int rl = mrow + mf * 16;
            #pragma unroll
            for (int nf = 0; nf < 8; nf++) {
                const int ccol = (wid >> 2) * 64 + nf * 8 + tig * 2;
                #pragma unroll
                for (int e = 0; e < 4; e++) {
                    float a = acc[mf][nf][e];
                    int d = ccol + (e & 1);
                    int m = rl + (e >> 1) * 8;
                    __nv_bfloat16 h = __float2bfloat16(a);
                    __nv_bfloat16 l = __float2bfloat16(a - __bfloat162float(h));
                    svh[d * 136 + m] = h;
                    svl[d * 136 + m] = l;
                }
            }
        }
        __syncthreads();
        const int b  = m0 >> 11;
        const int t0 = m0 & 2047;
        #pragma unroll
        for (int i = 0; i < 16; i++) {
            int c = tid + i * 256;
            int cc = c & 2047;
            int d = cc >> 4, col = cc & 15;
            const __nv_bfloat16* src = (c < 2048 ? svh : svl) + d * 136 + col * 8;
            __nv_bfloat16* dst = (c < 2048 ? g_Vth : g_Vtl)
                                 + ((size_t)b * NH + d) * NT + t0 + col * 8;
            *(float4*)dst = *(const float4*)src;
        }
    }
}

// ===========================================================================
// Flash attention with mma.sync bf16 split (unchanged from round 9/10).
// ===========================================================================
#define ATTN_SMEM 110592

__device__ __forceinline__ void load_K_tile(uint32_t sb, int b, int kt, int st, int tid) {
    const __nv_bfloat16* kh = g_Kh + ((size_t)b * NT + kt * 32) * NH;
    const __nv_bfloat16* kl = g_Kl + ((size_t)b * NT + kt * 32) * NH;
    uint32_t base = sb + 34816u + (uint32_t)st * 17408u;
    #pragma unroll
    for (int i = 0; i < 8; i++) {
        int c = tid + i * 128;
        int cc = c & 511;
        int row = cc >> 4, col = cc & 15;
        const __nv_bfloat16* src = (c < 512 ? kh : kl) + row * NH + col * 8;
        uint32_t dst = base + (c < 512 ? 0u : 8704u) + row * 272 + col * 16;
        CPA16(dst, src);
    }
}
__device__ __forceinline__ void load_V_tile(uint32_t sb, int b, int kt, int st, int tid) {
    const __nv_bfloat16* vh = g_Vth + (size_t)b * NH * NT + kt * 32;
    const __nv_bfloat16* vl = g_Vtl + (size_t)b * NH * NT + kt * 32;
    uint32_t base = sb + 69632u + (uint32_t)st * 20480u;
    #pragma unroll
    for (int i = 0; i < 8; i++) {
        int c = tid + i * 128;
        int cc = c & 511;
        int row = cc >> 2, col = cc & 3;
        const __nv_bfloat16* src = (c < 512 ? vh : vl) + (size_t)row * NT + col * 8;
        uint32_t dst = base + (c < 512 ? 0u : 10240u) + row * 80 + col * 16;
        CPA16(dst, src);
    }
}

__global__ __launch_bounds__(128, 2)
void attn_kernel(float* __restrict__ out) {
    extern __shared__ char smc[];
    const uint32_t sb = smem_u32(smc);

    // Exact-cover balanced mapping (each (qtile,b) once)
    const int bid = (int)blockIdx.x;
    int qtile, b;
    if (bid < 104)      { qtile = bid >> 3;                b = bid & 7; }
    else if (bid < 108) { qtile = 13;                      b = bid - 104; }
    else if (bid < 148) { qtile = 27 + ((bid - 108) >> 3); b = (bid - 108) & 7; }
    else if (bid < 252) { qtile = 26 - ((bid - 148) >> 3); b = (bid - 148) & 7; }
    else                { qtile = 13;                      b = bid - 252 + 4; }
    const int q0  = qtile * 64;
    const int NKT = 2 * qtile + 2;

    const int tid  = threadIdx.x;
    const int lane = tid & 31;
    const int band = tid >> 5;
    const int g    = lane >> 2;
    const int tig  = lane & 3;

    {
        const __nv_bfloat16* qh = g_Qh + ((size_t)b * NT + q0) * NH;
        const __nv_bfloat16* ql = g_Ql + ((size_t)b * NT + q0) * NH;
        #pragma unroll
        for (int i = 0; i < 16; i++) {
            int c = tid + i * 128;
            int cc = c & 1023;
            int row = cc >> 4, col = cc & 15;
            const __nv_bfloat16* src = (c < 1024 ? qh : ql) + row * NH + col * 8;
            uint32_t dst = sb + (c < 1024 ? 0u : 17408u) + row * 272 + col * 16;
            CPA16(dst, src);
        }
        load_K_tile(sb, b, 0, 0, tid);
    }
    CP_COMMIT;
    load_V_tile(sb, b, 0, 0, tid);
    load_K_tile(sb, b, 1, 1, tid);
    CP_COMMIT;
    CP_WAIT(1);
    __syncthreads();

    float m0 = -INFINITY, m1 = -INFINITY, l0 = 0.f, l1 = 0.f;
    float oacc[16][4];
    #pragma unroll
    for (int n = 0; n < 16; n++)
        #pragma unroll
        for (int e = 0; e < 4; e++) oacc[n][e] = 0.f;

    const int r0a = q0 + band * 16 + g;
    const char* qbase = smc + (band * 16 + g) * 272 + tig * 4;

    for (int kt = 0; kt < NKT; kt++) {
        const int st = kt & 1;
        const char* Kbase = smc + 34816 + st * 17408;
        const char* Vbase = smc + 69632 + st * 20480;

        float cf[4][4];
        #pragma unroll
        for (int nf = 0; nf < 4; nf++)
            #pragma unroll
            for (int e = 0; e < 4; e++) cf[nf][e] = 0.f;

        #pragma unroll
        for (int ks = 0; ks < 8; ks++) {
            const char* qp = qbase + ks * 32;
            uint32_t qhf[4] = { *(const uint32_t*)qp,
                                *(const uint32_t*)(qp + 8*272),
                                *(const uint32_t*)(qp + 16),
                                *(const uint32_t*)(qp + 8*272 + 16) };
            uint32_t qlf[4] = { *(const uint32_t*)(qp + 17408),
                                *(const uint32_t*)(qp + 17408 + 8*272),
                                *(const uint32_t*)(qp + 17408 + 16),
                                *(const uint32_t*)(qp + 17408 + 8*272 + 16) };
            #pragma unroll
            for (int nf = 0; nf < 4; nf++) {
                const char* kp = Kbase + (nf * 8 + g) * 272 + ks * 32 + tig * 4;
                uint32_t bh[2] = { *(const uint32_t*)kp, *(const uint32_t*)(kp + 16) };
                uint32_t bl[2] = { *(const uint32_t*)(kp + 8704),
                                   *(const uint32_t*)(kp + 8704 + 16) };
                mma_bf16(cf[nf], qhf, bh);
                mma_bf16(cf[nf], qhf, bl);
                mma_bf16(cf[nf], qlf, bh);
            }
        }

        const int k0 = kt * 32;
        if (k0 + 31 > r0a) {
            #pragma unroll
            for (int nf = 0; nf < 4; nf++) {
                int cb = k0 + nf * 8 + 2 * tig;
                if (cb     > r0a)     cf[nf][0] = -INFINITY;
                if (cb + 1 > r0a)     cf[nf][1] = -INFINITY;
                if (cb     > r0a + 8) cf[nf][2] = -INFINITY;
                if (cb + 1 > r0a + 8) cf[nf][3] = -INFINITY;
            }
        }

        float rx0 = -INFINITY, rx1 = -INFINITY;
        #pragma unroll
        for (int nf = 0; nf < 4; nf++) {
            rx0 = fmaxf(rx0, fmaxf(cf[nf][0], cf[nf][1]));
            rx1 = fmaxf(rx1, fmaxf(cf[nf][2], cf[nf][3]));
        }
        rx0 = fmaxf(rx0, __shfl_xor_sync(0xffffffffu, rx0, 1));
        rx0 = fmaxf(rx0, __shfl_xor_sync(0xffffffffu, rx0, 2));
        rx1 = fmaxf(rx1, __shfl_xor_sync(0xffffffffu, rx1, 1));
        rx1 = fmaxf(rx1, __shfl_xor_sync(0xffffffffu, rx1, 2));
        float mn0 = fmaxf(m0, rx0), mn1 = fmaxf(m1, rx1);
        float al0 = (m0 == -INFINITY) ? 0.f : __expf(m0 - mn0);
        float al1 = (m1 == -INFINITY) ? 0.f : __expf(m1 - mn1);
        float rs0 = 0.f, rs1 = 0.f;
        #pragma unroll
        for (int nf = 0; nf < 4; nf++) {
            cf[nf][0] = (cf[nf][0] == -INFINITY) ? 0.f : __expf(cf[nf][0] - mn0);
            cf[nf][1] = (cf[nf][1] == -INFINITY) ? 0.f : __expf(cf[nf][1] - mn0);
            cf[nf][2] = (cf[nf][2] == -INFINITY) ? 0.f : __expf(cf[nf][2] - mn1);
            cf[nf][3] = (cf[nf][3] == -INFINITY) ? 0.f : __expf(cf[nf][3] - mn1);
            rs0 += cf[nf][0] + cf[nf][1];
            rs1 += cf[nf][2] + cf[nf][3];
        }
        rs0 += __shfl_xor_sync(0xffffffffu, rs0, 1);
        rs0 += __shfl_xor_sync(0xffffffffu, rs0, 2);
        rs1 += __shfl_xor_sync(0xffffffffu, rs1, 1);
        rs1 += __shfl_xor_sync(0xffffffffu, rs1, 2);
        m0 = mn0; m1 = mn1;
        l0 = l0 * al0 + rs0;
        l1 = l1 * al1 + rs1;

        #pragma unroll
        for (int n = 0; n < 16; n++) {
            oacc[n][0] *= al0; oacc[n][1] *= al0;
            oacc[n][2] *= al1; oacc[n][3] *= al1;
        }

        uint32_t pah[2][4], pal[2][4];
        #pragma unroll
        for (int kc = 0; kc < 2; kc++) {
            bsplit2(cf[2*kc][0],   cf[2*kc][1],   pah[kc][0], pal[kc][0]);
            bsplit2(cf[2*kc][2],   cf[2*kc][3],   pah[kc][1], pal[kc][1]);
            bsplit2(cf[2*kc+1][0], cf[2*kc+1][1], pah[kc][2], pal[kc][2]);
            bsplit2(cf[2*kc+1][2], cf[2*kc+1][3], pah[kc][3], pal[kc][3]);
        }

        __syncthreads();
        if (kt + 2 < NKT) load_K_tile(sb, b, kt + 2, st, tid);
        if (kt + 1 < NKT) load_V_tile(sb, b, kt + 1, st ^ 1, tid);
        CP_COMMIT;
        CP_WAIT(1);
        __syncthreads();

        #pragma unroll
        for (int n = 0; n < 16; n++) {
            #pragma unroll
            for (int kc = 0; kc < 2; kc++) {
                const char* vp = Vbase + (n * 8 + g) * 80 + kc * 32 + tig * 4;
                uint32_t bh[2] = { *(const uint32_t*)vp, *(const uint32_t*)(vp + 16) };
                uint32_t bl[2] = { *(const uint32_t*)(vp + 10240),
                                   *(const uint32_t*)(vp + 10240 + 16) };
                mma_bf16(oacc[n], pah[kc], bh);
                mma_bf16(oacc[n], pah[kc], bl);
                mma_bf16(oacc[n], pal[kc], bh);
            }
        }
    }

    const float il0 = 1.f / l0, il1 = 1.f / l1;
    float* Og  = out + ((size_t)b * NT + q0 + band * 16 + g) * NH;
    float* Og8 = Og + 8 * NH;
    #pragma unroll
    for (int n = 0; n < 16; n++) {
        const int cc = n * 8 + 2 * tig;
        *(float2*)&Og[cc]  = make_float2(oacc[n][0] * il0, oacc[n][1] * il0);
        *(float2*)&Og8[cc] = make_float2(oacc[n][2] * il1, oacc[n][3] * il1);
    }
}

// ---------------------------------------------------------------------------
extern "C" void kernel_launch(void* const* d_in, const int* in_sizes, int n_in,
                              void* d_out, int out_size) {
    const float* x  = (const float*)d_in[0];
    const float* Wq = (const float*)d_in[1];
    const float* Wk = (const float*)d_in[2];
    const float* Wv = (const float*)d_in[3];
    float* out = (float*)d_out;

    split_pass<<<XBLK + 3 * WBLK, 256>>>(x, Wq, Wk, Wv);

    cudaFuncSetAttribute(qkv_mma_kernel,
                         cudaFuncAttributeMaxDynamicSharedMemorySize, QKV_SMEM);
    qkv_mma_kernel<<<dim3(NBT / 128, 3), 256, QKV_SMEM>>>();

    cudaFuncSetAttribute(attn_kernel,
                         cudaFuncAttributeMaxDynamicSharedMemorySize, ATTN_SMEM);
    attn_kernel<<<256, 128, ATTN_SMEM>>>(out);
}

// round 13
// speedup vs baseline: 1.0013x; 1.0013x over previous
#include <cuda_runtime.h>
#include <cuda_bf16.h>
#include <math.h>
#include <stdint.h>

#define NB 8
#define NT 2048
#define NC 1024
#define NH 128
#define NBT (NB*NT)

// bf16 hi/lo split scratch
__device__ __nv_bfloat16 g_Xh[NBT*NC];    // x hi/lo planes (from split_pass)
__device__ __nv_bfloat16 g_Xl[NBT*NC];
__device__ __nv_bfloat16 g_Wh[3*NH*NC];   // Wq|Wk|Wv hi/lo planes
__device__ __nv_bfloat16 g_Wl[3*NH*NC];
__device__ __nv_bfloat16 g_Qh[NBT*NH];    // Q * scale, [b][t][d]
__device__ __nv_bfloat16 g_Ql[NBT*NH];
__device__ __nv_bfloat16 g_Kh[NBT*NH];    // [b][t][d]
__device__ __nv_bfloat16 g_Kl[NBT*NH];
__device__ __nv_bfloat16 g_Vth[NB*NH*NT]; // transposed: [b][d][t]
__device__ __nv_bfloat16 g_Vtl[NB*NH*NT];

// ===========================================================================
// Helpers (generic sm_80+ PTX)
// ===========================================================================
__device__ __forceinline__ void mma_bf16(float* d, const uint32_t* a, const uint32_t* b) {
    asm volatile(
        "mma.sync.aligned.m16n8k16.row.col.f32.bf16.bf16.f32 "
        "{%0,%1,%2,%3}, {%4,%5,%6,%7}, {%8,%9}, {%0,%1,%2,%3};"
        : "+f"(d[0]), "+f"(d[1]), "+f"(d[2]), "+f"(d[3])
        : "r"(a[0]), "r"(a[1]), "r"(a[2]), "r"(a[3]), "r"(b[0]), "r"(b[1]));
}
__device__ __forceinline__ void bsplit2(float x, float y, uint32_t& h, uint32_t& l) {
    __nv_bfloat162 hh = __floats2bfloat162_rn(x, y);
    float rx = x - __bfloat162float(hh.x);
    float ry = y - __bfloat162float(hh.y);
    __nv_bfloat162 ll = __floats2bfloat162_rn(rx, ry);
    h = *(uint32_t*)&hh;
    l = *(uint32_t*)&ll;
}
__device__ __forceinline__ uint32_t smem_u32(const void* p) {
    uint32_t a;
    asm("{ .reg .u64 t; cvta.to.shared.u64 t, %1; cvt.u32.u64 %0, t; }" : "=r"(a) : "l"(p));
    return a;
}
#define CPA16(dst, src) \
    asm volatile("cp.async.cg.shared.global [%0], [%1], 16;" :: "r"(dst), "l"(src))
#define CP_COMMIT asm volatile("cp.async.commit_group;" ::: "memory")
#define CP_WAIT(n) asm volatile("cp.async.wait_group %0;" :: "n"(n) : "memory")

// ===========================================================================
// Pre-pass: convert x and W to bf16 hi/lo planes (once). ~20us, HBM-bound.
// ===========================================================================
#define XBLK (NBT * NC / 4 / 256)      // 16384
#define WBLK (NH * NC / 4 / 256)       // 128 per weight matrix

__global__ __launch_bounds__(256, 8)
void split_pass(const float* __restrict__ x,
                const float* __restrict__ Wq,
                const float* __restrict__ Wk,
                const float* __restrict__ Wv) {
    const int bid = (int)blockIdx.x;
    const int tid = threadIdx.x;
    if (bid < XBLK) {
        size_t i = (size_t)bid * 256 + tid;          // float4 index
        float4 v = ((const float4*)x)[i];
        uint32_t h0, l0, h1, l1;
        bsplit2(v.x, v.y, h0, l0);
        bsplit2(v.z, v.w, h1, l1);
        ((uint2*)g_Xh)[i] = make_uint2(h0, h1);
        ((uint2*)g_Xl)[i] = make_uint2(l0, l1);
    } else {
        const int j = bid - XBLK;                    // 0..383
        const int widx = j / WBLK;
        const float* W = (widx == 0) ? Wq : (widx == 1) ? Wk : Wv;
        size_t i = (size_t)(j % WBLK) * 256 + tid;   // float4 idx within W
        float4 v = ((const float4*)W)[i];
        uint32_t h0, l0, h1, l1;
        bsplit2(v.x, v.y, h0, l0);
        bsplit2(v.z, v.w, h1, l1);
        size_t o = (size_t)widx * (NH * NC / 4) + i;
        ((uint2*)g_Wh)[o] = make_uint2(h0, h1);
        ((uint2*)g_Wl)[o] = make_uint2(l0, l1);
    }
}

// ===========================================================================
// QKV projection, bf16 3-term split GEMM (m16n8k16), pure cp.async mainloop.
// LINEAR grid, widx = bid % 3: the three widx-CTAs sharing an x-tile have
// adjacent bids -> same wave -> x-plane reads are L2-temporal (x HBM 3x -> 1x).
// ===========================================================================
#define ROWW 20                       // u32 words per plane row (40 bf16)
#define PLANE (128 * ROWW)            // 2560 u32 per plane
#define STAGEW (4 * PLANE)            // words per stage
#define STAGEB (STAGEW * 4)           // 40960 bytes
#define QKV_SMEM (2 * STAGEB)         // 81920 bytes

__device__ __forceinline__ void qkv_load_stage(uint32_t sb, int st, int m0,
                                               int widx, int k0, int tid) {
    #pragma unroll
    for (int i = 0; i < 8; i++) {
        int c = tid + i * 256;
        int plane = c >> 9;                 // 0:Ah 1:Al 2:Bh 3:Bl
        int cc = c & 511;
        int row = cc >> 2, ch = cc & 3;
        const __nv_bfloat16* src;
        if (plane == 0)      src = g_Xh + (size_t)(m0 + row) * NC + k0 + ch * 8;
        else if (plane == 1) src = g_Xl + (size_t)(m0 + row) * NC + k0 + ch * 8;
        else if (plane == 2) src = g_Wh + ((size_t)widx * NH + row) * NC + k0 + ch * 8;
        else                 src = g_Wl + ((size_t)widx * NH + row) * NC + k0 + ch * 8;
        uint32_t dst = sb + (uint32_t)st * STAGEB + plane * (PLANE * 4) + row * 80 + ch * 16;
        CPA16(dst, src);
    }
}

__global__ __launch_bounds__(256, 2)
void qkv_mma_kernel() {
    extern __shared__ uint32_t smu[];
    const uint32_t sb = smem_u32(smu);

    const int bid  = (int)blockIdx.x;
    const int widx = bid % 3;                 // adjacent bids share the x tile
    const int m0   = (bid / 3) * 128;

    const int tid  = threadIdx.x;
    const int wid  = tid >> 5;
    const int lane = tid & 31;
    const int g    = lane >> 2;
    const int tig  = lane & 3;

    qkv_load_stage(sb, 0, m0, widx, 0, tid);
    CP_COMMIT;
    qkv_load_stage(sb, 1, m0, widx, 32, tid);
    CP_COMMIT;

    float acc[2][8][4];
    #pragma unroll
    for (int mf = 0; mf < 2; mf++)
        #pragma unroll
        for (int nf = 0; nf < 8; nf++)
            #pragma unroll
            for (int i = 0; i < 4; i++) acc[mf][nf][i] = 0.f;

    const int mrow  = (wid & 3) * 32 + g;
    const int nbase = (wid >> 2) * 64 + g;

    for (int c = 0; c < 32; c++) {
        const int st = c & 1;
        const uint32_t* Ah = smu + st * STAGEW;
        const uint32_t* Al = Ah + PLANE;
        const uint32_t* Bh = Ah + 2 * PLANE;
        const uint32_t* Bl = Ah + 3 * PLANE;

        CP_WAIT(1);          // chunk c's stage complete
        __syncthreads();

        #pragma unroll
        for (int ks = 0; ks < 2; ks++) {
            const int ko = ks * 8 + tig;
            uint32_t ahf[2][4], alf[2][4];
            #pragma unroll
            for (int mf = 0; mf < 2; mf++) {
                const int base = (mrow + mf * 16) * ROWW + ko;
                ahf[mf][0] = Ah[base];
                ahf[mf][1] = Ah[base + 8 * ROWW];
                ahf[mf][2] = Ah[base + 4];
                ahf[mf][3] = Ah[base + 8 * ROWW + 4];
                alf[mf][0] = Al[base];
                alf[mf][1] = Al[base + 8 * ROWW];
                alf[mf][2] = Al[base + 4];
                alf[mf][3] = Al[base + 8 * ROWW + 4];
            }
            #pragma unroll
            for (int nf = 0; nf < 8; nf++) {
                const int bb = (nbase + nf * 8) * ROWW + ko;
                uint32_t bh[2] = { Bh[bb], Bh[bb + 4] };
                uint32_t bl[2] = { Bl[bb], Bl[bb + 4] };
                #pragma unroll
                for (int mf = 0; mf < 2; mf++) {
                    mma_bf16(acc[mf][nf], ahf[mf], bh);
                    mma_bf16(acc[mf][nf], ahf[mf], bl);
                    mma_bf16(acc[mf][nf], alf[mf], bh);
                }
            }
        }

        __syncthreads();     // all warps done reading stage before overwrite
        if (c + 2 < 32) qkv_load_stage(sb, st, m0, widx, (c + 2) * 32, tid);
        CP_COMMIT;           // uniform group cadence
    }

    // ---- epilogue: bf16 hi/lo outputs for the attention kernel ----
    if (widx < 2) {
        __nv_bfloat16* oh = (widx == 0) ? g_Qh : g_Kh;
        __nv_bfloat16* ol = (widx == 0) ? g_Ql : g_Kl;
        const float sc = (widx == 0) ? 0.08838834764831845f : 1.0f;
        #pragma unroll
        for (int mf = 0; mf < 2; mf++) {
            const int crow = m0 + mrow + mf * 16;
            #pragma unroll
            for (int nf = 0; nf < 8; nf++) {
                const int ccol = (wid >> 2) * 64 + nf * 8 + tig * 2;
                uint32_t h01, l01, h23, l23;
                bsplit2(acc[mf][nf][0]*sc, acc[mf][nf][1]*sc, h01, l01);
                bsplit2(acc[mf][nf][2]*sc, acc[mf][nf][3]*sc, h23, l23);
                *(uint32_t*)&oh[(size_t)crow * NH + ccol]       = h01;
                *(uint32_t*)&ol[(size_t)crow * NH + ccol]       = l01;
                *(uint32_t*)&oh[(size_t)(crow + 8) * NH + ccol] = h23;
                *(uint32_t*)&ol[(size_t)(crow + 8) * NH + ccol] = l23;
            }
        }
    } else {
        // V: transpose to [d][t] via smem, then coalesced writes
        __nv_bfloat16* svh = (__nv_bfloat16*)smu;      // [128 d][136]
        __nv_bfloat16* svl = svh + 128 * 136;
        __syncthreads();
        #pragma unroll
        for (int mf = 0; mf < 2; mf++) {
            const int rl = mrow + mf * 16;
            #pragma unroll
            for (int nf = 0; nf < 8; nf++) {
                const int ccol = (wid >> 2) * 64 + nf * 8 + tig * 2;
                #pragma unroll
                for (int e = 0; e < 4; e++) {
                    float a = acc[mf][nf][e];
                    int d = ccol + (e & 1);
                    int m = rl + (e >> 1) * 8;
                    __nv_bfloat16 h = __float2bfloat16(a);
                    __nv_bfloat16 l = __float2bfloat16(a - __bfloat162float(h));
                    svh[d * 136 + m] = h;
                    svl[d * 136 + m] = l;
                }
            }
        }
        __syncthreads();
        const int b  = m0 >> 11;
        const int t0 = m0 & 2047;
        #pragma unroll
        for (int i = 0; i < 16; i++) {
            int c = tid + i * 256;
            int cc = c & 2047;
            int d = cc >> 4, col = cc & 15;
            const __nv_bfloat16* src = (c < 2048 ? svh : svl) + d * 136 + col * 8;
            __nv_bfloat16* dst = (c < 2048 ? g_Vth : g_Vtl)
                                 + ((size_t)b * NH + d) * NT + t0 + col * 8;
            *(float4*)dst = *(const float4*)src;
        }
    }
}

// ===========================================================================
// Flash attention with mma.sync bf16 split (unchanged from round 9/10; 144us).
// ===========================================================================
#define ATTN_SMEM 110592

__device__ __forceinline__ void load_K_tile(uint32_t sb, int b, int kt, int st, int tid) {
    const __nv_bfloat16* kh = g_Kh + ((size_t)b * NT + kt * 32) * NH;
    const __nv_bfloat16* kl = g_Kl + ((size_t)b * NT + kt * 32) * NH;
    uint32_t base = sb + 34816u + (uint32_t)st * 17408u;
    #pragma unroll
    for (int i = 0; i < 8; i++) {
        int c = tid + i * 128;
        int cc = c & 511;
        int row = cc >> 4, col = cc & 15;
        const __nv_bfloat16* src = (c < 512 ? kh : kl) + row * NH + col * 8;
        uint32_t dst = base + (c < 512 ? 0u : 8704u) + row * 272 + col * 16;
        CPA16(dst, src);
    }
}
__device__ __forceinline__ void load_V_tile(uint32_t sb, int b, int kt, int st, int tid) {
    const __nv_bfloat16* vh = g_Vth + (size_t)b * NH * NT + kt * 32;
    const __nv_bfloat16* vl = g_Vtl + (size_t)b * NH * NT + kt * 32;
    uint32_t base = sb + 69632u + (uint32_t)st * 20480u;
    #pragma unroll
    for (int i = 0; i < 8; i++) {
        int c = tid + i * 128;
        int cc = c & 511;
        int row = cc >> 2, col = cc & 3;
        const __nv_bfloat16* src = (c < 512 ? vh : vl) + (size_t)row * NT + col * 8;
        uint32_t dst = base + (c < 512 ? 0u : 10240u) + row * 80 + col * 16;
        CPA16(dst, src);
    }
}

__global__ __launch_bounds__(128, 2)
void attn_kernel(float* __restrict__ out) {
    extern __shared__ char smc[];
    const uint32_t sb = smem_u32(smc);

    // Exact-cover balanced mapping (each (qtile,b) once)
    const int bid = (int)blockIdx.x;
    int qtile, b;
    if (bid < 104)      { qtile = bid >> 3;                b = bid & 7; }
    else if (bid < 108) { qtile = 13;                      b = bid - 104; }
    else if (bid < 148) { qtile = 27 + ((bid - 108) >> 3); b = (bid - 108) & 7; }
    else if (bid < 252) { qtile = 26 - ((bid - 148) >> 3); b = (bid - 148) & 7; }
    else                { qtile = 13;                      b = bid - 252 + 4; }
    const int q0  = qtile * 64;
    const int NKT = 2 * qtile + 2;

    const int tid  = threadIdx.x;
    const int lane = tid & 31;
    const int band = tid >> 5;
    const int g    = lane >> 2;
    const int tig  = lane & 3;

    {
        const __nv_bfloat16* qh = g_Qh + ((size_t)b * NT + q0) * NH;
        const __nv_bfloat16* ql = g_Ql + ((size_t)b * NT + q0) * NH;
        #pragma unroll
        for (int i = 0; i < 16; i++) {
            int c = tid + i * 128;
            int cc = c & 1023;
            int row = cc >> 4, col = cc & 15;
            const __nv_bfloat16* src = (c < 1024 ? qh : ql) + row * NH + col * 8;
            uint32_t dst = sb + (c < 1024 ? 0u : 17408u) + row * 272 + col * 16;
            CPA16(dst, src);
        }
        load_K_tile(sb, b, 0, 0, tid);
    }
    CP_COMMIT;
    load_V_tile(sb, b, 0, 0, tid);
    load_K_tile(sb, b, 1, 1, tid);
    CP_COMMIT;
    CP_WAIT(1);
    __syncthreads();

    float m0 = -INFINITY, m1 = -INFINITY, l0 = 0.f, l1 = 0.f;
    float oacc[16][4];
    #pragma unroll
    for (int n = 0; n < 16; n++)
        #pragma unroll
        for (int e = 0; e < 4; e++) oacc[n][e] = 0.f;

    const int r0a = q0 + band * 16 + g;
    const char* qbase = smc + (band * 16 + g) * 272 + tig * 4;

    for (int kt = 0; kt < NKT; kt++) {
        const int st = kt & 1;
        const char* Kbase = smc + 34816 + st * 17408;
        const char* Vbase = smc + 69632 + st * 20480;

        float cf[4][4];
        #pragma unroll
        for (int nf = 0; nf < 4; nf++)
            #pragma unroll
            for (int e = 0; e < 4; e++) cf[nf][e] = 0.f;

        #pragma unroll
        for (int ks = 0; ks < 8; ks++) {
            const char* qp = qbase + ks * 32;
            uint32_t qhf[4] = { *(const uint32_t*)qp,
                                *(const uint32_t*)(qp + 8*272),
                                *(const uint32_t*)(qp + 16),
                                *(const uint32_t*)(qp + 8*272 + 16) };
            uint32_t qlf[4] = { *(const uint32_t*)(qp + 17408),
                                *(const uint32_t*)(qp + 17408 + 8*272),
                                *(const uint32_t*)(qp + 17408 + 16),
                                *(const uint32_t*)(qp + 17408 + 8*272 + 16) };
            #pragma unroll
            for (int nf = 0; nf < 4; nf++) {
                const char* kp = Kbase + (nf * 8 + g) * 272 + ks * 32 + tig * 4;
                uint32_t bh[2] = { *(const uint32_t*)kp, *(const uint32_t*)(kp + 16) };
                uint32_t bl[2] = { *(const uint32_t*)(kp + 8704),
                                   *(const uint32_t*)(kp + 8704 + 16) };
                mma_bf16(cf[nf], qhf, bh);
                mma_bf16(cf[nf], qhf, bl);
                mma_bf16(cf[nf], qlf, bh);
            }
        }

        const int k0 = kt * 32;
        if (k0 + 31 > r0a) {
            #pragma unroll
            for (int nf = 0; nf < 4; nf++) {
                int cb = k0 + nf * 8 + 2 * tig;
                if (cb     > r0a)     cf[nf][0] = -INFINITY;
                if (cb + 1 > r0a)     cf[nf][1] = -INFINITY;
                if (cb     > r0a + 8) cf[nf][2] = -INFINITY;
                if (cb + 1 > r0a + 8) cf[nf][3] = -INFINITY;
            }
        }

        float rx0 = -INFINITY, rx1 = -INFINITY;
        #pragma unroll
        for (int nf = 0; nf < 4; nf++) {
            rx0 = fmaxf(rx0, fmaxf(cf[nf][0], cf[nf][1]));
            rx1 = fmaxf(rx1, fmaxf(cf[nf][2], cf[nf][3]));
        }
        rx0 = fmaxf(rx0, __shfl_xor_sync(0xffffffffu, rx0, 1));
        rx0 = fmaxf(rx0, __shfl_xor_sync(0xffffffffu, rx0, 2));
        rx1 = fmaxf(rx1, __shfl_xor_sync(0xffffffffu, rx1, 1));
        rx1 = fmaxf(rx1, __shfl_xor_sync(0xffffffffu, rx1, 2));
        float mn0 = fmaxf(m0, rx0), mn1 = fmaxf(m1, rx1);
        float al0 = (m0 == -INFINITY) ? 0.f : __expf(m0 - mn0);
        float al1 = (m1 == -INFINITY) ? 0.f : __expf(m1 - mn1);
        float rs0 = 0.f, rs1 = 0.f;
        #pragma unroll
        for (int nf = 0; nf < 4; nf++) {
            cf[nf][0] = (cf[nf][0] == -INFINITY) ? 0.f : __expf(cf[nf][0] - mn0);
            cf[nf][1] = (cf[nf][1] == -INFINITY) ? 0.f : __expf(cf[nf][1] - mn0);
            cf[nf][2] = (cf[nf][2] == -INFINITY) ? 0.f : __expf(cf[nf][2] - mn1);
            cf[nf][3] = (cf[nf][3] == -INFINITY) ? 0.f : __expf(cf[nf][3] - mn1);
            rs0 += cf[nf][0] + cf[nf][1];
            rs1 += cf[nf][2] + cf[nf][3];
        }
        rs0 += __shfl_xor_sync(0xffffffffu, rs0, 1);
        rs0 += __shfl_xor_sync(0xffffffffu, rs0, 2);
        rs1 += __shfl_xor_sync(0xffffffffu, rs1, 1);
        rs1 += __shfl_xor_sync(0xffffffffu, rs1, 2);
        m0 = mn0; m1 = mn1;
        l0 = l0 * al0 + rs0;
        l1 = l1 * al1 + rs1;

        #pragma unroll
        for (int n = 0; n < 16; n++) {
            oacc[n][0] *= al0; oacc[n][1] *= al0;
            oacc[n][2] *= al1; oacc[n][3] *= al1;
        }

        uint32_t pah[2][4], pal[2][4];
        #pragma unroll
        for (int kc = 0; kc < 2; kc++) {
            bsplit2(cf[2*kc][0],   cf[2*kc][1],   pah[kc][0], pal[kc][0]);
            bsplit2(cf[2*kc][2],   cf[2*kc][3],   pah[kc][1], pal[kc][1]);
            bsplit2(cf[2*kc+1][0], cf[2*kc+1][1], pah[kc][2], pal[kc][2]);
            bsplit2(cf[2*kc+1][2], cf[2*kc+1][3], pah[kc][3], pal[kc][3]);
        }

        __syncthreads();
        if (kt + 2 < NKT) load_K_tile(sb, b, kt + 2, st, tid);
        if (kt + 1 < NKT) load_V_tile(sb, b, kt + 1, st ^ 1, tid);
        CP_COMMIT;
        CP_WAIT(1);
        __syncthreads();

        #pragma unroll
        for (int n = 0; n < 16; n++) {
            #pragma unroll
            for (int kc = 0; kc < 2; kc++) {
                const char* vp = Vbase + (n * 8 + g) * 80 + kc * 32 + tig * 4;
                uint32_t bh[2] = { *(const uint32_t*)vp, *(const uint32_t*)(vp + 16) };
                uint32_t bl[2] = { *(const uint32_t*)(vp + 10240),
                                   *(const uint32_t*)(vp + 10240 + 16) };
                mma_bf16(oacc[n], pah[kc], bh);
                mma_bf16(oacc[n], pah[kc], bl);
                mma_bf16(oacc[n], pal[kc], bh);
            }
        }
    }

    const float il0 = 1.f / l0, il1 = 1.f / l1;
    float* Og  = out + ((size_t)b * NT + q0 + band * 16 + g) * NH;
    float* Og8 = Og + 8 * NH;
    #pragma unroll
    for (int n = 0; n < 16; n++) {
        const int cc = n * 8 + 2 * tig;
        *(float2*)&Og[cc]  = make_float2(oacc[n][0] * il0, oacc[n][1] * il0);
        *(float2*)&Og8[cc] = make_float2(oacc[n][2] * il1, oacc[n][3] * il1);
    }
}

// ---------------------------------------------------------------------------
extern "C" void kernel_launch(void* const* d_in, const int* in_sizes, int n_in,
                              void* d_out, int out_size) {
    const float* x  = (const float*)d_in[0];
    const float* Wq = (const float*)d_in[1];
    const float* Wk = (const float*)d_in[2];
    const float* Wv = (const float*)d_in[3];
    float* out = (float*)d_out;

    split_pass<<<XBLK + 3 * WBLK, 256>>>(x, Wq, Wk, Wv);

    cudaFuncSetAttribute(qkv_mma_kernel,
                         cudaFuncAttributeMaxDynamicSharedMemorySize, QKV_SMEM);
    qkv_mma_kernel<<<3 * (NBT / 128), 256, QKV_SMEM>>>();

    cudaFuncSetAttribute(attn_kernel,
                         cudaFuncAttributeMaxDynamicSharedMemorySize, ATTN_SMEM);
    attn_kernel<<<256, 128, ATTN_SMEM>>>(out);
}

// round 15
// speedup vs baseline: 1.0132x; 1.0119x over previous
#include <cuda_runtime.h>
#include <cuda_bf16.h>
#include <math.h>
#include <stdint.h>

#define NB 8
#define NT 2048
#define NC 1024
#define NH 128
#define NBT (NB*NT)

// bf16 hi/lo split scratch
__device__ __nv_bfloat16 g_Xh[NBT*NC];
__device__ __nv_bfloat16 g_Xl[NBT*NC];
__device__ __nv_bfloat16 g_Wh[3*NH*NC];
__device__ __nv_bfloat16 g_Wl[3*NH*NC];
__device__ __nv_bfloat16 g_Qh[NBT*NH];
__device__ __nv_bfloat16 g_Ql[NBT*NH];
__device__ __nv_bfloat16 g_Kh[NBT*NH];
__device__ __nv_bfloat16 g_Kl[NBT*NH];
__device__ __nv_bfloat16 g_Vth[NB*NH*NT];
__device__ __nv_bfloat16 g_Vtl[NB*NH*NT];

// ===========================================================================
// Helpers (generic sm_80+ PTX)
// ===========================================================================
__device__ __forceinline__ void mma_bf16(float* d, const uint32_t* a, const uint32_t* b) {
    asm volatile(
        "mma.sync.aligned.m16n8k16.row.col.f32.bf16.bf16.f32 "
        "{%0,%1,%2,%3}, {%4,%5,%6,%7}, {%8,%9}, {%0,%1,%2,%3};"
        : "+f"(d[0]), "+f"(d[1]), "+f"(d[2]), "+f"(d[3])
        : "r"(a[0]), "r"(a[1]), "r"(a[2]), "r"(a[3]), "r"(b[0]), "r"(b[1]));
}
__device__ __forceinline__ void ldm_x4(uint32_t* r, uint32_t a) {
    asm volatile("ldmatrix.sync.aligned.m8n8.x4.shared.b16 {%0,%1,%2,%3}, [%4];"
        : "=r"(r[0]), "=r"(r[1]), "=r"(r[2]), "=r"(r[3]) : "r"(a));
}
__device__ __forceinline__ void bsplit2(float x, float y, uint32_t& h, uint32_t& l) {
    __nv_bfloat162 hh = __floats2bfloat162_rn(x, y);
    float rx = x - __bfloat162float(hh.x);
    float ry = y - __bfloat162float(hh.y);
    __nv_bfloat162 ll = __floats2bfloat162_rn(rx, ry);
    h = *(uint32_t*)&hh;
    l = *(uint32_t*)&ll;
}
__device__ __forceinline__ uint32_t smem_u32(const void* p) {
    uint32_t a;
    asm("{ .reg .u64 t; cvta.to.shared.u64 t, %1; cvt.u32.u64 %0, t; }" : "=r"(a) : "l"(p));
    return a;
}
#define CPA16(dst, src) \
    asm volatile("cp.async.cg.shared.global [%0], [%1], 16;" :: "r"(dst), "l"(src))
#define CP_COMMIT asm volatile("cp.async.commit_group;" ::: "memory")
#define CP_WAIT(n) asm volatile("cp.async.wait_group %0;" :: "n"(n) : "memory")

// ===========================================================================
// Pre-pass: convert x and W to bf16 hi/lo planes (once). ~20us, HBM-bound.
// ===========================================================================
#define XBLK (NBT * NC / 4 / 256)
#define WBLK (NH * NC / 4 / 256)

__global__ __launch_bounds__(256, 8)
void split_pass(const float* __restrict__ x,
                const float* __restrict__ Wq,
                const float* __restrict__ Wk,
                const float* __restrict__ Wv) {
    const int bid = (int)blockIdx.x;
    const int tid = threadIdx.x;
    if (bid < XBLK) {
        size_t i = (size_t)bid * 256 + tid;
        float4 v = ((const float4*)x)[i];
        uint32_t h0, l0, h1, l1;
        bsplit2(v.x, v.y, h0, l0);
        bsplit2(v.z, v.w, h1, l1);
        ((uint2*)g_Xh)[i] = make_uint2(h0, h1);
        ((uint2*)g_Xl)[i] = make_uint2(l0, l1);
    } else {
        const int j = bid - XBLK;
        const int widx = j / WBLK;
        const float* W = (widx == 0) ? Wq : (widx == 1) ? Wk : Wv;
        size_t i = (size_t)(j % WBLK) * 256 + tid;
        float4 v = ((const float4*)W)[i];
        uint32_t h0, l0, h1, l1;
        bsplit2(v.x, v.y, h0, l0);
        bsplit2(v.z, v.w, h1, l1);
        size_t o = (size_t)widx * (NH * NC / 4) + i;
        ((uint2*)g_Wh)[o] = make_uint2(h0, h1);
        ((uint2*)g_Wl)[o] = make_uint2(l0, l1);
    }
}

// ===========================================================================
// QKV projection, bf16 3-term split GEMM, ldmatrix fragment loads.
// ===========================================================================
#define ROWW 20                       // u32 words per plane row (40 bf16)
#define PLANE (128 * ROWW)
#define PLANE4 (PLANE * 4)            // plane size in bytes
#define STAGEW (4 * PLANE)
#define STAGEB (STAGEW * 4)           // 40960 bytes
#define QKV_SMEM (2 * STAGEB)

__device__ __forceinline__ void qkv_load_stage(uint32_t sb, int st, int m0,
                                               int widx, int k0, int tid) {
    #pragma unroll
    for (int i = 0; i < 8; i++) {
        int c = tid + i * 256;
        int plane = c >> 9;
        int cc = c & 511;
        int row = cc >> 2, ch = cc & 3;
        const __nv_bfloat16* src;
        if (plane == 0)      src = g_Xh + (size_t)(m0 + row) * NC + k0 + ch * 8;
        else if (plane == 1) src = g_Xl + (size_t)(m0 + row) * NC + k0 + ch * 8;
        else if (plane == 2) src = g_Wh + ((size_t)widx * NH + row) * NC + k0 + ch * 8;
        else                 src = g_Wl + ((size_t)widx * NH + row) * NC + k0 + ch * 8;
        uint32_t dst = sb + (uint32_t)st * STAGEB + plane * PLANE4 + row * 80 + ch * 16;
        CPA16(dst, src);
    }
}

__global__ __launch_bounds__(256, 2)
void qkv_mma_kernel() {
    extern __shared__ uint32_t smu[];
    const uint32_t sb = smem_u32(smu);

    const int bid  = (int)blockIdx.x;
    const int widx = bid % 3;
    const int m0   = (bid / 3) * 128;

    const int tid  = threadIdx.x;
    const int wid  = tid >> 5;
    const int lane = tid & 31;
    const int g    = lane >> 2;
    const int tig  = lane & 3;

    qkv_load_stage(sb, 0, m0, widx, 0, tid);
    CP_COMMIT;
    qkv_load_stage(sb, 1, m0, widx, 32, tid);
    CP_COMMIT;

    float acc[2][8][4];
    #pragma unroll
    for (int mf = 0; mf < 2; mf++)
        #pragma unroll
        for (int nf = 0; nf < 8; nf++)
            #pragma unroll
            for (int i = 0; i < 4; i++) acc[mf][nf][i] = 0.f;

    const int mrow  = (wid & 3) * 32 + g;        // for epilogue
    // A x4 tile order: [rows0-7,c0][rows8-15,c0][rows0-7,c16][rows8-15,c16]
    const uint32_t offA = (uint32_t)(((wid & 3) * 32 + (lane & 7) + ((lane >> 3) & 1) * 8) * 80
                                     + ((lane >> 4) & 1) * 16);
    // B x4 tile order: [nf rows,c0][nf rows,c16][nf+1 rows,c0][nf+1 rows,c16]
    const uint32_t offB = (uint32_t)(((wid >> 2) * 64 + (lane & 7) + ((lane >> 4) & 1) * 8) * 80
                                     + ((lane >> 3) & 1) * 16);

    for (int c = 0; c < 32; c++) {
        const int st = c & 1;
        const uint32_t stage = sb + (uint32_t)st * STAGEB;

        CP_WAIT(1);
        __syncthreads();

        #pragma unroll
        for (int ks = 0; ks < 2; ks++) {
            uint32_t ahf[2][4], alf[2][4];
            #pragma unroll
            for (int mf = 0; mf < 2; mf++) {
                uint32_t a = stage + offA + mf * (16 * 80) + ks * 32;
                ldm_x4(ahf[mf], a);
                ldm_x4(alf[mf], a + PLANE4);
            }
            #pragma unroll
            for (int nfp = 0; nfp < 4; nfp++) {
                uint32_t bAddr = stage + 2 * PLANE4 + offB + nfp * (16 * 80) + ks * 32;
                uint32_t bh4[4], bl4[4];
                ldm_x4(bh4, bAddr);
                ldm_x4(bl4, bAddr + PLANE4);
                #pragma unroll
                for (int mf = 0; mf < 2; mf++) {
                    mma_bf16(acc[mf][2*nfp],   ahf[mf], bh4);
                    mma_bf16(acc[mf][2*nfp],   ahf[mf], bl4);
                    mma_bf16(acc[mf][2*nfp],   alf[mf], bh4);
                    mma_bf16(acc[mf][2*nfp+1], ahf[mf], bh4 + 2);
                    mma_bf16(acc[mf][2*nfp+1], ahf[mf], bl4 + 2);
                    mma_bf16(acc[mf][2*nfp+1], alf[mf], bh4 + 2);
                }
            }
        }

        __syncthreads();
        if (c + 2 < 32) qkv_load_stage(sb, st, m0, widx, (c + 2) * 32, tid);
        CP_COMMIT;
    }

    // ---- epilogue: bf16 hi/lo outputs for the attention kernel ----
    if (widx < 2) {
        __nv_bfloat16* oh = (widx == 0) ? g_Qh : g_Kh;
        __nv_bfloat16* ol = (widx == 0) ? g_Ql : g_Kl;
        const float sc = (widx == 0) ? 0.08838834764831845f : 1.0f;
        #pragma unroll
        for (int mf = 0; mf < 2; mf++) {
            const int crow = m0 + mrow + mf * 16;
            #pragma unroll
            for (int nf = 0; nf < 8; nf++) {
                const int ccol = (wid >> 2) * 64 + nf * 8 + tig * 2;
                uint32_t h01, l01, h23, l23;
                bsplit2(acc[mf][nf][0]*sc, acc[mf][nf][1]*sc, h01, l01);
                bsplit2(acc[mf][nf][2]*sc, acc[mf][nf][3]*sc, h23, l23);
                *(uint32_t*)&oh[(size_t)crow * NH + ccol]       = h01;
                *(uint32_t*)&ol[(size_t)crow * NH + ccol]       = l01;
                *(uint32_t*)&oh[(size_t)(crow + 8) * NH + ccol] = h23;
                *(uint32_t*)&ol[(size_t)(crow + 8) * NH + ccol] = l23;
            }
        }
    } else {
        __nv_bfloat16* svh = (__nv_bfloat16*)smu;      // [128 d][136]
        __nv_bfloat16* svl = svh + 128 * 136;
        __syncthreads();
        #pragma unroll
        for (int mf = 0; mf < 2; mf++) {
            const int rl = mrow + mf * 16;
            #pragma unroll
            for (int nf = 0; nf < 8; nf++) {
                const int ccol = (wid >> 2) * 64 + nf * 8 + tig * 2;
                #pragma unroll
                for (int e = 0; e < 4; e++) {
                    float a = acc[mf][nf][e];
                    int d = ccol + (e & 1);
                    int m = rl + (e >> 1) * 8;
                    __nv_bfloat16 h = __float2bfloat16(a);
                    __nv_bfloat16 l = __float2bfloat16(a - __bfloat162float(h));
                    svh[d * 136 + m] = h;
                    svl[d * 136 + m] = l;
                }
            }
        }
        __syncthreads();
        const int b  = m0 >> 11;
        const int t0 = m0 & 2047;
        #pragma unroll
        for (int i = 0; i < 16; i++) {
            int c = tid + i * 256;
            int cc = c & 2047;
            int d = cc >> 4, col = cc & 15;
            const __nv_bfloat16* src = (c < 2048 ? svh : svl) + d * 136 + col * 8;
            __nv_bfloat16* dst = (c < 2048 ? g_Vth : g_Vtl)
                                 + ((size_t)b * NH + d) * NT + t0 + col * 8;
            *(float4*)dst = *(const float4*)src;
        }
    }
}

// ===========================================================================
// Flash attention, bf16 split + ldmatrix fragment loads.
// ===========================================================================
#define ATTN_SMEM 110592

__device__ __forceinline__ void load_K_tile(uint32_t sb, int b, int kt, int st, int tid) {
    const __nv_bfloat16* kh = g_Kh + ((size_t)b * NT + kt * 32) * NH;
    const __nv_bfloat16* kl = g_Kl + ((size_t)b * NT + kt * 32) * NH;
    uint32_t base = sb + 34816u + (uint32_t)st * 17408u;
    #pragma unroll
    for (int i = 0; i < 8; i++) {
        int c = tid + i * 128;
        int cc = c & 511;
        int row = cc >> 4, col = cc & 15;
        const __nv_bfloat16* src = (c < 512 ? kh : kl) + row * NH + col * 8;
        uint32_t dst = base + (c < 512 ? 0u : 8704u) + row * 272 + col * 16;
        CPA16(dst, src);
    }
}
__device__ __forceinline__ void load_V_tile(uint32_t sb, int b, int kt, int st, int tid) {
    const __nv_bfloat16* vh = g_Vth + (size_t)b * NH * NT + kt * 32;
    const __nv_bfloat16* vl = g_Vtl + (size_t)b * NH * NT + kt * 32;
    uint32_t base = sb + 69632u + (uint32_t)st * 20480u;
    #pragma unroll
    for (int i = 0; i < 8; i++) {
        int c = tid + i * 128;
        int cc = c & 511;
        int row = cc >> 2, col = cc & 3;
        const __nv_bfloat16* src = (c < 512 ? vh : vl) + (size_t)row * NT + col * 8;
        uint32_t dst = base + (c < 512 ? 0u : 10240u) + row * 80 + col * 16;
        CPA16(dst, src);
    }
}

__global__ __launch_bounds__(128, 2)
void attn_kernel(float* __restrict__ out) {
    extern __shared__ char smc[];
    const uint32_t sb = smem_u32(smc);

    // Exact-cover balanced mapping (each (qtile,b) once)
    const int bid = (int)blockIdx.x;
    int qtile, b;
    if (bid < 104)      { qtile = bid >> 3;                b = bid & 7; }
    else if (bid < 108) { qtile = 13;                      b = bid - 104; }
    else if (bid < 148) { qtile = 27 + ((bid - 108) >> 3); b = (bid - 108) & 7; }
    else if (bid < 252) { qtile = 26 - ((bid - 148) >> 3); b = (bid - 148) & 7; }
    else                { qtile = 13;                      b = bid - 252 + 4; }
    const int q0  = qtile * 64;
    const int NKT = 2 * qtile + 2;

    const int tid  = threadIdx.x;
    const int lane = tid & 31;
    const int band = tid >> 5;
    const int g    = lane >> 2;
    const int tig  = lane & 3;

    {
        const __nv_bfloat16* qh = g_Qh + ((size_t)b * NT + q0) * NH;
        const __nv_bfloat16* ql = g_Ql + ((size_t)b * NT + q0) * NH;
        #pragma unroll
        for (int i = 0; i < 16; i++) {
            int c = tid + i * 128;
            int cc = c & 1023;
            int row = cc >> 4, col = cc & 15;
            const __nv_bfloat16* src = (c < 1024 ? qh : ql) + row * NH + col * 8;
            uint32_t dst = sb + (c < 1024 ? 0u : 17408u) + row * 272 + col * 16;
            CPA16(dst, src);
        }
        load_K_tile(sb, b, 0, 0, tid);
    }
    CP_COMMIT;
    load_V_tile(sb, b, 0, 0, tid);
    load_K_tile(sb, b, 1, 1, tid);
    CP_COMMIT;
    CP_WAIT(1);
    __syncthreads();

    float m0 = -INFINITY, m1 = -INFINITY, l0 = 0.f, l1 = 0.f;
    float oacc[16][4];
    #pragma unroll
    for (int n = 0; n < 16; n++)
        #pragma unroll
        for (int e = 0; e < 4; e++) oacc[n][e] = 0.f;

    const int r0a = q0 + band * 16 + g;

    // ldmatrix per-lane address components
    const uint32_t offQ = (uint32_t)((band * 16 + (lane & 7) + ((lane >> 3) & 1) * 8) * 272
                                     + ((lane >> 4) & 1) * 16);
    const uint32_t offK = (uint32_t)(((lane & 7) + ((lane >> 4) & 1) * 8) * 272
                                     + ((lane >> 3) & 1) * 16);
    const uint32_t offV = (uint32_t)((lane & 7) * 80 + (lane >> 3) * 16);

    for (int kt = 0; kt < NKT; kt++) {
        const int st = kt & 1;
        const uint32_t Kb = sb + 34816u + (uint32_t)st * 17408u;
        const uint32_t Vb = sb + 69632u + (uint32_t)st * 20480u;

        float cf[4][4];
        #pragma unroll
        for (int nf = 0; nf < 4; nf++)
            #pragma unroll
            for (int e = 0; e < 4; e++) cf[nf][e] = 0.f;

        #pragma unroll
        for (int ks = 0; ks < 8; ks++) {
            uint32_t qa = sb + offQ + ks * 32;
            uint32_t qhf[4], qlf[4];
            ldm_x4(qhf, qa);
            ldm_x4(qlf, qa + 17408u);
            #pragma unroll
            for (int nfp = 0; nfp < 2; nfp++) {
                uint32_t ka = Kb + offK + nfp * (16 * 272) + ks * 32;
                uint32_t kh4[4], kl4[4];
                ldm_x4(kh4, ka);
                ldm_x4(kl4, ka + 8704u);
                mma_bf16(cf[2*nfp],   qhf, kh4);
                mma_bf16(cf[2*nfp],   qhf, kl4);
                mma_bf16(cf[2*nfp],   qlf, kh4);
                mma_bf16(cf[2*nfp+1], qhf, kh4 + 2);
                mma_bf16(cf[2*nfp+1], qhf, kl4 + 2);
                mma_bf16(cf[2*nfp+1], qlf, kh4 + 2);
            }
        }

        const int k0 = kt * 32;
        if (k0 + 31 > r0a) {
            #pragma unroll
            for (int nf = 0; nf < 4; nf++) {
                int cb = k0 + nf * 8 + 2 * tig;
                if (cb     > r0a)     cf[nf][0] = -INFINITY;
                if (cb + 1 > r0a)     cf[nf][1] = -INFINITY;
                if (cb     > r0a + 8) cf[nf][2] = -INFINITY;
                if (cb + 1 > r0a + 8) cf[nf][3] = -INFINITY;
            }
        }

        float rx0 = -INFINITY, rx1 = -INFINITY;
        #pragma unroll
        for (int nf = 0; nf < 4; nf++) {
            rx0 = fmaxf(rx0, fmaxf(cf[nf][0], cf[nf][1]));
            rx1 = fmaxf(rx1, fmaxf(cf[nf][2], cf[nf][3]));
        }
        rx0 = fmaxf(rx0, __shfl_xor_sync(0xffffffffu, rx0, 1));
        rx0 = fmaxf(rx0, __shfl_xor_sync(0xffffffffu, rx0, 2));
        rx1 = fmaxf(rx1, __shfl_xor_sync(0xffffffffu, rx1, 1));
        rx1 = fmaxf(rx1, __shfl_xor_sync(0xffffffffu, rx1, 2));
        float mn0 = fmaxf(m0, rx0), mn1 = fmaxf(m1, rx1);
        float al0 = (m0 == -INFINITY) ? 0.f : __expf(m0 - mn0);
        float al1 = (m1 == -INFINITY) ? 0.f : __expf(m1 - mn1);
        float rs0 = 0.f, rs1 = 0.f;
        #pragma unroll
        for (int nf = 0; nf < 4; nf++) {
            cf[nf][0] = (cf[nf][0] == -INFINITY) ? 0.f : __expf(cf[nf][0] - mn0);
            cf[nf][1] = (cf[nf][1] == -INFINITY) ? 0.f : __expf(cf[nf][1] - mn0);
            cf[nf][2] = (cf[nf][2] == -INFINITY) ? 0.f : __expf(cf[nf][2] - mn1);
            cf[nf][3] = (cf[nf][3] == -INFINITY) ? 0.f : __expf(cf[nf][3] - mn1);
            rs0 += cf[nf][0] + cf[nf][1];
            rs1 += cf[nf][2] + cf[nf][3];
        }
        rs0 += __shfl_xor_sync(0xffffffffu, rs0, 1);
        rs0 += __shfl_xor_sync(0xffffffffu, rs0, 2);
        rs1 += __shfl_xor_sync(0xffffffffu, rs1, 1);
        rs1 += __shfl_xor_sync(0xffffffffu, rs1, 2);
        m0 = mn0; m1 = mn1;
        l0 = l0 * al0 + rs0;
        l1 = l1 * al1 + rs1;

        #pragma unroll
        for (int n = 0; n < 16; n++) {
            oacc[n][0] *= al0; oacc[n][1] *= al0;
            oacc[n][2] *= al1; oacc[n][3] *= al1;
        }

        uint32_t pah[2][4], pal[2][4];
        #pragma unroll
        for (int kc = 0; kc < 2; kc++) {
            bsplit2(cf[2*kc][0],   cf[2*kc][1],   pah[kc][0], pal[kc][0]);
            bsplit2(cf[2*kc][2],   cf[2*kc][3],   pah[kc][1], pal[kc][1]);
            bsplit2(cf[2*kc+1][0], cf[2*kc+1][1], pah[kc][2], pal[kc][2]);
            bsplit2(cf[2*kc+1][2], cf[2*kc+1][3], pah[kc][3], pal[kc][3]);
        }

        __syncthreads();
        if (kt + 2 < NKT) load_K_tile(sb, b, kt + 2, st, tid);
        if (kt + 1 < NKT) load_V_tile(sb, b, kt + 1, st ^ 1, tid);
        CP_COMMIT;
        CP_WAIT(1);
        __syncthreads();

        #pragma unroll
        for (int n = 0; n < 16; n++) {
            uint32_t va = Vb + offV + n * (8 * 80);
            uint32_t vh4[4], vl4[4];
            ldm_x4(vh4, va);
            ldm_x4(vl4, va + 10240u);
            #pragma unroll
            for (int kc = 0; kc < 2; kc++) {
                mma_bf16(oacc[n], pah[kc], vh4 + 2*kc);
                mma_bf16(oacc[n], pah[kc], vl4 + 2*kc);
                mma_bf16(oacc[n], pal[kc], vh4 + 2*kc);
            }
        }
    }

    const float il0 = 1.f / l0, il1 = 1.f / l1;
    float* Og  = out + ((size_t)b * NT + q0 + band * 16 + g) * NH;
    float* Og8 = Og + 8 * NH;
    #pragma unroll
    for (int n = 0; n < 16; n++) {
        const int cc = n * 8 + 2 * tig;
        *(float2*)&Og[cc]  = make_float2(oacc[n][0] * il0, oacc[n][1] * il0);
        *(float2*)&Og8[cc] = make_float2(oacc[n][2] * il1, oacc[n][3] * il1);
    }
}

// ---------------------------------------------------------------------------
extern "C" void kernel_launch(void* const* d_in, const int* in_sizes, int n_in,
                              void* d_out, int out_size) {
    const float* x  = (const float*)d_in[0];
    const float* Wq = (const float*)d_in[1];
    const float* Wk = (const float*)d_in[2];
    const float* Wv = (const float*)d_in[3];
    float* out = (float*)d_out;

    split_pass<<<XBLK + 3 * WBLK, 256>>>(x, Wq, Wk, Wv);

    cudaFuncSetAttribute(qkv_mma_kernel,
                         cudaFuncAttributeMaxDynamicSharedMemorySize, QKV_SMEM);
    qkv_mma_kernel<<<3 * (NBT / 128), 256, QKV_SMEM>>>();

    cudaFuncSetAttribute(attn_kernel,
                         cudaFuncAttributeMaxDynamicSharedMemorySize, ATTN_SMEM);
    attn_kernel<<<256, 128, ATTN_SMEM>>>(out);
}

// round 16
// speedup vs baseline: 2.2431x; 2.2138x over previous
#include <cuda_runtime.h>
#include <cuda_fp16.h>
#include <math.h>
#include <stdint.h>

#define NB 8
#define NT 2048
#define NC 1024
#define NH 128
#define NBT (NB*NT)

// fp16 scratch
__device__ __half g_Xf[NBT*NC];    // x fp16 (from split_pass)
__device__ __half g_Wf[3*NH*NC];   // Wq|Wk|Wv fp16
__device__ __half g_Qf[NBT*NH];    // Q * scale, [b][t][d]
__device__ __half g_Kf[NBT*NH];    // [b][t][d]
__device__ __half g_Vtf[NB*NH*NT]; // V transposed: [b][d][t]

// ===========================================================================
// Helpers (generic sm_80+ PTX)
// ===========================================================================
__device__ __forceinline__ void mma_f16(float* d, const uint32_t* a, const uint32_t* b) {
    asm volatile(
        "mma.sync.aligned.m16n8k16.row.col.f32.f16.f16.f32 "
        "{%0,%1,%2,%3}, {%4,%5,%6,%7}, {%8,%9}, {%0,%1,%2,%3};"
        : "+f"(d[0]), "+f"(d[1]), "+f"(d[2]), "+f"(d[3])
        : "r"(a[0]), "r"(a[1]), "r"(a[2]), "r"(a[3]), "r"(b[0]), "r"(b[1]));
}
__device__ __forceinline__ void ldm_x4(uint32_t* r, uint32_t a) {
    asm volatile("ldmatrix.sync.aligned.m8n8.x4.shared.b16 {%0,%1,%2,%3}, [%4];"
        : "=r"(r[0]), "=r"(r[1]), "=r"(r[2]), "=r"(r[3]) : "r"(a));
}
__device__ __forceinline__ uint32_t pack_h2(float x, float y) {
    __half2 h = __floats2half2_rn(x, y);
    return *(uint32_t*)&h;
}
__device__ __forceinline__ uint32_t smem_u32(const void* p) {
    uint32_t a;
    asm("{ .reg .u64 t; cvta.to.shared.u64 t, %1; cvt.u32.u64 %0, t; }" : "=r"(a) : "l"(p));
    return a;
}
#define CPA16(dst, src) \
    asm volatile("cp.async.cg.shared.global [%0], [%1], 16;" :: "r"(dst), "l"(src))
#define CP_COMMIT asm volatile("cp.async.commit_group;" ::: "memory")
#define CP_WAIT(n) asm volatile("cp.async.wait_group %0;" :: "n"(n) : "memory")

// ===========================================================================
// Pre-pass: convert x and W to fp16 (once). HBM-bound, ~13us.
// ===========================================================================
#define XBLK (NBT * NC / 4 / 256)      // 16384
#define WBLK (NH * NC / 4 / 256)       // 128 per W

__global__ __launch_bounds__(256, 8)
void split_pass(const float* __restrict__ x,
                const float* __restrict__ Wq,
                const float* __restrict__ Wk,
                const float* __restrict__ Wv) {
    const int bid = (int)blockIdx.x;
    const int tid = threadIdx.x;
    if (bid < XBLK) {
        size_t i = (size_t)bid * 256 + tid;
        float4 v = ((const float4*)x)[i];
        ((uint2*)g_Xf)[i] = make_uint2(pack_h2(v.x, v.y), pack_h2(v.z, v.w));
    } else {
        const int j = bid - XBLK;
        const int widx = j / WBLK;
        const float* W = (widx == 0) ? Wq : (widx == 1) ? Wk : Wv;
        size_t i = (size_t)(j % WBLK) * 256 + tid;
        float4 v = ((const float4*)W)[i];
        size_t o = (size_t)widx * (NH * NC / 4) + i;
        ((uint2*)g_Wf)[o] = make_uint2(pack_h2(v.x, v.y), pack_h2(v.z, v.w));
    }
}

// ===========================================================================
// QKV projection, fp16 single-term GEMM (m16n8k16), cp.async mainloop.
// CTA 128x128, K chunk 32, 2 stages. Planes A,B [128 rows][80B pad].
// ===========================================================================
#define PLANE4 10240                  // 128 * 80 bytes
#define STAGEB (2 * PLANE4)           // 20480
#define QKV_SMEM (2 * STAGEB)         // 40960

__device__ __forceinline__ void qkv_load_stage(uint32_t sb, int st, int m0,
                                               int widx, int k0, int tid) {
    #pragma unroll
    for (int i = 0; i < 4; i++) {
        int c = tid + i * 256;             // 1024 chunks of 16B
        int plane = c >> 9;                // 0:A 1:B
        int cc = c & 511;
        int row = cc >> 2, ch = cc & 3;
        const __half* src = (plane == 0)
            ? g_Xf + (size_t)(m0 + row) * NC + k0 + ch * 8
            : g_Wf + ((size_t)widx * NH + row) * NC + k0 + ch * 8;
        uint32_t dst = sb + (uint32_t)st * STAGEB + plane * PLANE4 + row * 80 + ch * 16;
        CPA16(dst, src);
    }
}

__global__ __launch_bounds__(256, 2)
void qkv_mma_kernel() {
    extern __shared__ uint32_t smu[];
    const uint32_t sb = smem_u32(smu);

    const int bid  = (int)blockIdx.x;
    const int widx = bid % 3;
    const int m0   = (bid / 3) * 128;

    const int tid  = threadIdx.x;
    const int wid  = tid >> 5;
    const int lane = tid & 31;
    const int g    = lane >> 2;
    const int tig  = lane & 3;

    qkv_load_stage(sb, 0, m0, widx, 0, tid);
    CP_COMMIT;
    qkv_load_stage(sb, 1, m0, widx, 32, tid);
    CP_COMMIT;

    float acc[2][8][4];
    #pragma unroll
    for (int mf = 0; mf < 2; mf++)
        #pragma unroll
        for (int nf = 0; nf < 8; nf++)
            #pragma unroll
            for (int i = 0; i < 4; i++) acc[mf][nf][i] = 0.f;

    const int mrow = (wid & 3) * 32 + g;
    const uint32_t offA = (uint32_t)(((wid & 3) * 32 + (lane & 7) + ((lane >> 3) & 1) * 8) * 80
                                     + ((lane >> 4) & 1) * 16);
    const uint32_t offB = (uint32_t)(((wid >> 2) * 64 + (lane & 7) + ((lane >> 4) & 1) * 8) * 80
                                     + ((lane >> 3) & 1) * 16);

    for (int c = 0; c < 32; c++) {
        const int st = c & 1;
        const uint32_t stage = sb + (uint32_t)st * STAGEB;

        CP_WAIT(1);
        __syncthreads();

        #pragma unroll
        for (int ks = 0; ks < 2; ks++) {
            uint32_t af[2][4];
            #pragma unroll
            for (int mf = 0; mf < 2; mf++)
                ldm_x4(af[mf], stage + offA + mf * (16 * 80) + ks * 32);
            #pragma unroll
            for (int nfp = 0; nfp < 4; nfp++) {
                uint32_t b4[4];
                ldm_x4(b4, stage + PLANE4 + offB + nfp * (16 * 80) + ks * 32);
                #pragma unroll
                for (int mf = 0; mf < 2; mf++) {
                    mma_f16(acc[mf][2*nfp],   af[mf], b4);
                    mma_f16(acc[mf][2*nfp+1], af[mf], b4 + 2);
                }
            }
        }

        __syncthreads();
        if (c + 2 < 32) qkv_load_stage(sb, st, m0, widx, (c + 2) * 32, tid);
        CP_COMMIT;
    }

    // ---- epilogue: fp16 outputs ----
    if (widx < 2) {
        __half* of = (widx == 0) ? g_Qf : g_Kf;
        const float sc = (widx == 0) ? 0.08838834764831845f : 1.0f;
        #pragma unroll
        for (int mf = 0; mf < 2; mf++) {
            const int crow = m0 + mrow + mf * 16;
            #pragma unroll
            for (int nf = 0; nf < 8; nf++) {
                const int ccol = (wid >> 2) * 64 + nf * 8 + tig * 2;
                *(uint32_t*)&of[(size_t)crow * NH + ccol] =
                    pack_h2(acc[mf][nf][0]*sc, acc[mf][nf][1]*sc);
                *(uint32_t*)&of[(size_t)(crow + 8) * NH + ccol] =
                    pack_h2(acc[mf][nf][2]*sc, acc[mf][nf][3]*sc);
            }
        }
    } else {
        // V transpose to [d][t] via smem, then coalesced writes
        __half* sv = (__half*)smu;             // [128 d][136]
        __syncthreads();
        #pragma unroll
        for (int mf = 0; mf < 2; mf++) {
            const int rl = mrow + mf * 16;
            #pragma unroll
            for (int nf = 0; nf < 8; nf++) {
                const int ccol = (wid >> 2) * 64 + nf * 8 + tig * 2;
                #pragma unroll
                for (int e = 0; e < 4; e++) {
                    int d = ccol + (e & 1);
                    int m = rl + (e >> 1) * 8;
                    sv[d * 136 + m] = __float2half(acc[mf][nf][e]);
                }
            }
        }
        __syncthreads();
        const int b  = m0 >> 11;
        const int t0 = m0 & 2047;
        #pragma unroll
        for (int i = 0; i < 8; i++) {
            int c = tid + i * 256;          // 2048 chunks of 16B
            int d = c >> 4, col = c & 15;
            *(float4*)(g_Vtf + ((size_t)b * NH + d) * NT + t0 + col * 8) =
                *(const float4*)(sv + d * 136 + col * 8);
        }
    }
}

// ===========================================================================
// Flash attention, fp16 single-term. 64-key tiles, 2 CTAs/SM.
// smem: Q[0,17408) K st[17408+st*17408) V st[52224+st*18432), total 89088.
// ===========================================================================
#define ATTN_SMEM 89088
#define KOFF 17408u
#define VOFF 52224u

__device__ __forceinline__ void load_K_tile(uint32_t sb, int b, int kt, int st, int tid) {
    const __half* kf = g_Kf + ((size_t)b * NT + kt * 64) * NH;
    uint32_t base = sb + KOFF + (uint32_t)st * 17408u;
    #pragma unroll
    for (int i = 0; i < 8; i++) {
        int c = tid + i * 128;             // 1024: 64 rows x 16 chunks
        int row = c >> 4, col = c & 15;
        CPA16(base + row * 272 + col * 16, kf + row * NH + col * 8);
    }
}
__device__ __forceinline__ void load_V_tile(uint32_t sb, int b, int kt, int st, int tid) {
    const __half* vf = g_Vtf + (size_t)b * NH * NT + kt * 64;
    uint32_t base = sb + VOFF + (uint32_t)st * 18432u;
    #pragma unroll
    for (int i = 0; i < 8; i++) {
        int c = tid + i * 128;             // 1024: 128 rows x 8 chunks
        int row = c >> 3, ch = c & 7;
        CPA16(base + row * 144 + ch * 16, vf + (size_t)row * NT + ch * 8);
    }
}

__global__ __launch_bounds__(128, 2)
void attn_kernel(float* __restrict__ out) {
    extern __shared__ char smc[];
    const uint32_t sb = smem_u32(smc);

    // Exact-cover balanced mapping (each (qtile,b) once)
    const int bid = (int)blockIdx.x;
    int qtile, b;
    if (bid < 104)      { qtile = bid >> 3;                b = bid & 7; }
    else if (bid < 108) { qtile = 13;                      b = bid - 104; }
    else if (bid < 148) { qtile = 27 + ((bid - 108) >> 3); b = (bid - 108) & 7; }
    else if (bid < 252) { qtile = 26 - ((bid - 148) >> 3); b = (bid - 148) & 7; }
    else                { qtile = 13;                      b = bid - 252 + 4; }
    const int q0  = qtile * 64;
    const int NKT = qtile + 1;            // 64-key tiles

    const int tid  = threadIdx.x;
    const int lane = tid & 31;
    const int band = tid >> 5;
    const int g    = lane >> 2;
    const int tig  = lane & 3;

    // prologue: group0 = Q + K0; group1 = V0 + K1
    {
        const __half* qf = g_Qf + ((size_t)b * NT + q0) * NH;
        #pragma unroll
        for (int i = 0; i < 8; i++) {
            int c = tid + i * 128;         // 1024: 64 rows x 16 chunks
            int row = c >> 4, col = c & 15;
            CPA16(sb + row * 272 + col * 16, qf + row * NH + col * 8);
        }
        load_K_tile(sb, b, 0, 0, tid);
    }
    CP_COMMIT;
    load_V_tile(sb, b, 0, 0, tid);
    if (NKT > 1) load_K_tile(sb, b, 1, 1, tid);
    CP_COMMIT;
    CP_WAIT(1);
    __syncthreads();

    float m0 = -INFINITY, m1 = -INFINITY, l0 = 0.f, l1 = 0.f;
    float oacc[16][4];
    #pragma unroll
    for (int n = 0; n < 16; n++)
        #pragma unroll
        for (int e = 0; e < 4; e++) oacc[n][e] = 0.f;

    const int r0a = q0 + band * 16 + g;

    const uint32_t offQ = (uint32_t)((band * 16 + (lane & 7) + ((lane >> 3) & 1) * 8) * 272
                                     + ((lane >> 4) & 1) * 16);
    const uint32_t offK = (uint32_t)(((lane & 7) + ((lane >> 4) & 1) * 8) * 272
                                     + ((lane >> 3) & 1) * 16);
    const uint32_t offV = (uint32_t)((lane & 7) * 144 + (lane >> 3) * 16);

    for (int kt = 0; kt < NKT; kt++) {
        const int st = kt & 1;
        const uint32_t Kb = sb + KOFF + (uint32_t)st * 17408u;
        const uint32_t Vb = sb + VOFF + (uint32_t)st * 18432u;

        // ---- S = Q K^T : warp tile 16 x 64, k = 128 ----
        float cf[8][4];
        #pragma unroll
        for (int nf = 0; nf < 8; nf++)
            #pragma unroll
            for (int e = 0; e < 4; e++) cf[nf][e] = 0.f;

        #pragma unroll
        for (int ks = 0; ks < 8; ks++) {
            uint32_t qf4[4];
            ldm_x4(qf4, sb + offQ + ks * 32);
            #pragma unroll
            for (int nfp = 0; nfp < 4; nfp++) {
                uint32_t k4[4];
                ldm_x4(k4, Kb + offK + nfp * (16 * 272) + ks * 32);
                mma_f16(cf[2*nfp],   qf4, k4);
                mma_f16(cf[2*nfp+1], qf4, k4 + 2);
            }
        }

        // ---- causal mask (only the diagonal tile) ----
        if (kt == qtile) {
            const int k0 = kt * 64;
            #pragma unroll
            for (int nf = 0; nf < 8; nf++) {
                int cb = k0 + nf * 8 + 2 * tig;
                if (cb     > r0a)     cf[nf][0] = -INFINITY;
                if (cb + 1 > r0a)     cf[nf][1] = -INFINITY;
                if (cb     > r0a + 8) cf[nf][2] = -INFINITY;
                if (cb + 1 > r0a + 8) cf[nf][3] = -INFINITY;
            }
        }

        // ---- online softmax (registers + quad shuffles) ----
        float rx0 = -INFINITY, rx1 = -INFINITY;
        #pragma unroll
        for (int nf = 0; nf < 8; nf++) {
            rx0 = fmaxf(rx0, fmaxf(cf[nf][0], cf[nf][1]));
            rx1 = fmaxf(rx1, fmaxf(cf[nf][2], cf[nf][3]));
        }
        rx0 = fmaxf(rx0, __shfl_xor_sync(0xffffffffu, rx0, 1));
        rx0 = fmaxf(rx0, __shfl_xor_sync(0xffffffffu, rx0, 2));
        rx1 = fmaxf(rx1, __shfl_xor_sync(0xffffffffu, rx1, 1));
        rx1 = fmaxf(rx1, __shfl_xor_sync(0xffffffffu, rx1, 2));
        float mn0 = fmaxf(m0, rx0), mn1 = fmaxf(m1, rx1);
        float al0 = (m0 == -INFINITY) ? 0.f : __expf(m0 - mn0);
        float al1 = (m1 == -INFINITY) ? 0.f : __expf(m1 - mn1);
        float rs0 = 0.f, rs1 = 0.f;
        #pragma unroll
        for (int nf = 0; nf < 8; nf++) {
            cf[nf][0] = (cf[nf][0] == -INFINITY) ? 0.f : __expf(cf[nf][0] - mn0);
            cf[nf][1] = (cf[nf][1] == -INFINITY) ? 0.f : __expf(cf[nf][1] - mn0);
            cf[nf][2] = (cf[nf][2] == -INFINITY) ? 0.f : __expf(cf[nf][2] - mn1);
            cf[nf][3] = (cf[nf][3] == -INFINITY) ? 0.f : __expf(cf[nf][3] - mn1);
            rs0 += cf[nf][0] + cf[nf][1];
            rs1 += cf[nf][2] + cf[nf][3];
        }
        rs0 += __shfl_xor_sync(0xffffffffu, rs0, 1);
        rs0 += __shfl_xor_sync(0xffffffffu, rs0, 2);
        rs1 += __shfl_xor_sync(0xffffffffu, rs1, 1);
        rs1 += __shfl_xor_sync(0xffffffffu, rs1, 2);
        m0 = mn0; m1 = mn1;
        l0 = l0 * al0 + rs0;
        l1 = l1 * al1 + rs1;

        #pragma unroll
        for (int n = 0; n < 16; n++) {
            oacc[n][0] *= al0; oacc[n][1] *= al0;
            oacc[n][2] *= al1; oacc[n][3] *= al1;
        }

        // P -> fp16 A-fragments (c-frag layout == A-frag layout), kc 0..3
        uint32_t pa[4][4];
        #pragma unroll
        for (int kc = 0; kc < 4; kc++) {
            pa[kc][0] = pack_h2(cf[2*kc][0],   cf[2*kc][1]);
            pa[kc][1] = pack_h2(cf[2*kc][2],   cf[2*kc][3]);
            pa[kc][2] = pack_h2(cf[2*kc+1][0], cf[2*kc+1][1]);
            pa[kc][3] = pack_h2(cf[2*kc+1][2], cf[2*kc+1][3]);
        }

        // rotate buffers: K(kt+2) -> st, V(kt+1) -> st^1
        __syncthreads();
        if (kt + 2 < NKT) load_K_tile(sb, b, kt + 2, st, tid);
        if (kt + 1 < NKT) load_V_tile(sb, b, kt + 1, st ^ 1, tid);
        CP_COMMIT;
        CP_WAIT(1);
        __syncthreads();

        // ---- O += P V : 16 n-frags, k = 64 ----
        #pragma unroll
        for (int n = 0; n < 16; n++) {
            uint32_t va = Vb + offV + n * (8 * 144);
            uint32_t v4a[4], v4b[4];
            ldm_x4(v4a, va);          // t 0..31
            ldm_x4(v4b, va + 64);     // t 32..63
            mma_f16(oacc[n], pa[0], v4a);
            mma_f16(oacc[n], pa[1], v4a + 2);
            mma_f16(oacc[n], pa[2], v4b);
            mma_f16(oacc[n], pa[3], v4b + 2);
        }
    }

    const float il0 = 1.f / l0, il1 = 1.f / l1;
    float* Og  = out + ((size_t)b * NT + q0 + band * 16 + g) * NH;
    float* Og8 = Og + 8 * NH;
    #pragma unroll
    for (int n = 0; n < 16; n++) {
        const int cc = n * 8 + 2 * tig;
        *(float2*)&Og[cc]  = make_float2(oacc[n][0] * il0, oacc[n][1] * il0);
        *(float2*)&Og8[cc] = make_float2(oacc[n][2] * il1, oacc[n][3] * il1);
    }
}

// ---------------------------------------------------------------------------
extern "C" void kernel_launch(void* const* d_in, const int* in_sizes, int n_in,
                              void* d_out, int out_size) {
    const float* x  = (const float*)d_in[0];
    const float* Wq = (const float*)d_in[1];
    const float* Wk = (const float*)d_in[2];
    const float* Wv = (const float*)d_in[3];
    float* out = (float*)d_out;

    split_pass<<<XBLK + 3 * WBLK, 256>>>(x, Wq, Wk, Wv);

    cudaFuncSetAttribute(qkv_mma_kernel,
                         cudaFuncAttributeMaxDynamicSharedMemorySize, QKV_SMEM);
    qkv_mma_kernel<<<3 * (NBT / 128), 256, QKV_SMEM>>>();

    cudaFuncSetAttribute(attn_kernel,
                         cudaFuncAttributeMaxDynamicSharedMemorySize, ATTN_SMEM);
    attn_kernel<<<256, 128, ATTN_SMEM>>>(out);
}